// round 15
// baseline (speedup 1.0000x reference)
#include <cuda_runtime.h>
#include <cuda_bf16.h>

// Tensor-core LSTM, R15: dual-stream warps. Each warp owns 16 batch elements
// as TWO independent groups of 8 (gates in M, batch in N, 16 MMAs per group
// per step). The two groups' dependency chains interleave inside one warp,
// filling the ~70% stall time R13 exposed. 128 CTAs x 64 thr: 2 warps/CTA,
// 256 active SMSPs, weights shared across groups (no redundant tensor work).

#define FULLMASK 0xffffffffu
#define LOG2E 1.4426950408889634f
#define H2C 0x3F003F00u   /* bf16x2 {0.5, 0.5} */

typedef unsigned int u32;

static __device__ __forceinline__ u32 packb2(float lo, float hi) {
    u32 d;
    asm("cvt.rn.bf16x2.f32 %0, %1, %2;" : "=r"(d) : "f"(hi), "f"(lo));
    return d;
}
static __device__ __forceinline__ u32 tanhb2(u32 x) {
    u32 y; asm("tanh.approx.bf16x2 %0, %1;" : "=r"(y) : "r"(x)); return y;
}
static __device__ __forceinline__ u32 mulb2(u32 a, u32 b) {
    u32 d; asm("mul.rn.bf16x2 %0, %1, %2;" : "=r"(d) : "r"(a), "r"(b)); return d;
}
static __device__ __forceinline__ u32 fmab2(u32 a, u32 b, u32 c) {
    u32 d; asm("fma.rn.bf16x2 %0, %1, %2, %3;" : "=r"(d) : "r"(a), "r"(b), "r"(c));
    return d;
}
static __device__ __forceinline__ float blo(u32 v) {
    return __uint_as_float(v << 16);
}
static __device__ __forceinline__ float bhi(u32 v) {
    return __uint_as_float(v & 0xFFFF0000u);
}
static __device__ __forceinline__ float ex2f(float x) {
    float y; asm("ex2.approx.f32 %0, %1;" : "=f"(y) : "f"(x)); return y;
}
static __device__ __forceinline__ float rcpf(float x) {
    float y; asm("rcp.approx.f32 %0, %1;" : "=f"(y) : "f"(x)); return y;
}
static __device__ __forceinline__ u32 movmat(u32 a) {
    u32 d;
    asm("movmatrix.sync.aligned.m8n8.trans.b16 %0, %1;" : "=r"(d) : "r"(a));
    return d;
}

// D = A @ B + {c0,c0,c1,c1}  (row-bias splat: rows g / g+8 of the tile)
static __device__ __forceinline__ void mma_c(
    float* d, u32 a0, u32 a1, u32 a2, u32 a3, u32 b0, u32 b1,
    float c0, float c1)
{
    asm("mma.sync.aligned.m16n8k16.row.col.f32.bf16.bf16.f32 "
        "{%0,%1,%2,%3},{%4,%5,%6,%7},{%8,%9},{%10,%10,%11,%11};"
        : "=f"(d[0]), "=f"(d[1]), "=f"(d[2]), "=f"(d[3])
        : "r"(a0), "r"(a1), "r"(a2), "r"(a3), "r"(b0), "r"(b1),
          "f"(c0), "f"(c1));
}
static __device__ __forceinline__ void mma_acc(
    float* d, u32 a0, u32 a1, u32 a2, u32 a3, u32 b0, u32 b1)
{
    asm("mma.sync.aligned.m16n8k16.row.col.f32.bf16.bf16.f32 "
        "{%0,%1,%2,%3},{%4,%5,%6,%7},{%8,%9},{%0,%1,%2,%3};"
        : "+f"(d[0]), "+f"(d[1]), "+f"(d[2]), "+f"(d[3])
        : "r"(a0), "r"(a1), "r"(a2), "r"(a3), "r"(b0), "r"(b1));
}

// packed 2-cell LSTM update; i/f/o gates PRE-SCALED by 0.5
#define PCELL(IP, FP, GP, OP, CC, HH) do {                                \
    u32 si_ = fmab2(tanhb2(IP), H2C, H2C);                                \
    u32 sf_ = fmab2(tanhb2(FP), H2C, H2C);                                \
    u32 tg_ = tanhb2(GP);                                                 \
    u32 so_ = fmab2(tanhb2(OP), H2C, H2C);                                \
    CC = fmab2(sf_, CC, mulb2(si_, tg_));                                 \
    HH = mulb2(so_, tanhb2(CC));                                          \
} while (0)

#define LAYER_CELLS(D, CP0, CP1, HP0, HP1) do {                           \
    u32 iP0 = packb2(D[0][0], D[0][1]), iP1 = packb2(D[0][2], D[0][3]);   \
    u32 fP0 = packb2(D[1][0], D[1][1]), fP1 = packb2(D[1][2], D[1][3]);   \
    u32 gP0 = packb2(D[2][0], D[2][1]), gP1 = packb2(D[2][2], D[2][3]);   \
    u32 oP0 = packb2(D[3][0], D[3][1]), oP1 = packb2(D[3][2], D[3][3]);   \
    PCELL(iP0, fP0, gP0, oP0, CP0, HP0);                                  \
    PCELL(iP1, fP1, gP1, oP1, CP1, HP1);                                  \
} while (0)

// 16 MMAs of one group-step: L2(i) into D2, L1(i+1) into D1
#define GROUP_MMAS(D2, D1, H1B0, H1B1, H2B0, H2B1, XB0, XB1) do {         \
    _Pragma("unroll")                                                     \
    for (int t = 0; t < 4; ++t) {                                         \
        mma_c  (D2[t], w2i[t][0], w2i[t][1], w2i[t][2], w2i[t][3],        \
                H1B0, H1B1, bs2f[t][0], bs2f[t][1]);                      \
        mma_acc(D2[t], w2h[t][0], w2h[t][1], w2h[t][2], w2h[t][3],        \
                H2B0, H2B1);                                              \
        mma_c  (D1[t], w1h[t][0], w1h[t][1], w1h[t][2], w1h[t][3],        \
                H1B0, H1B1, 0.f, 0.f);                                    \
        mma_acc(D1[t], w1i[t][0], w1i[t][1], w1i[t][2], w1i[t][3],        \
                XB0, XB1);                                                \
    }                                                                     \
} while (0)

__global__ void __launch_bounds__(64)
lstm_mma_kernel(const float* __restrict__ x,
                const float* __restrict__ Wih1, const float* __restrict__ Whh1,
                const float* __restrict__ bih1, const float* __restrict__ bhh1,
                const float* __restrict__ Wih2, const float* __restrict__ Whh2,
                const float* __restrict__ bih2, const float* __restrict__ bhh2,
                const float* __restrict__ Wd1, const float* __restrict__ bd1,
                const float* __restrict__ Wd2, const float* __restrict__ bd2,
                const float* __restrict__ Wd3, const float* __restrict__ bd3,
                float* __restrict__ out)
{
    constexpr int T = 512, IN = 11;
    const int tid  = threadIdx.x;
    const int lane = tid & 31;
    const int wid  = tid >> 5;           // 0..1
    const int q    = lane & 3;
    const int g    = lane >> 2;
    const int k0   = q * 2;
    const int eb   = blockIdx.x * 32;    // CTA batch base (32 elems)

    // x staging: [phase][step-in-chunk][elem][8 bf16x2]; chunk c holds t=4c+1..4c+4
    __shared__ __align__(16) u32 xs[2][4][32][8];
    __shared__ float sbuf[32][16];

    // ---- weight A-fragments (shared by both groups) ----
    u32 w1i[4][4], w1h[4][4], w2i[4][4], w2h[4][4];
    float bs2f[4][2];
#pragma unroll
    for (int t = 0; t < 4; ++t) {
        const float gs = (t == 2) ? 1.0f : 0.5f;
        const int r0 = t * 16 + g, r1 = r0 + 8;
        {
            float v00 = (k0     < IN) ? Wih1[r0 * IN + k0]     : 0.f;
            float v01 = (k0 + 1 < IN) ? Wih1[r0 * IN + k0 + 1] : 0.f;
            float v10 = (k0     < IN) ? Wih1[r1 * IN + k0]     : 0.f;
            float v11 = (k0 + 1 < IN) ? Wih1[r1 * IN + k0 + 1] : 0.f;
            float v08 = (k0 + 8 < IN) ? Wih1[r0 * IN + k0 + 8] : 0.f;
            float v09 = (k0 + 9 < IN) ? Wih1[r0 * IN + k0 + 9]
                      : (k0 + 9 == 11 ? (bih1[r0] + bhh1[r0]) : 0.f);
            float v18 = (k0 + 8 < IN) ? Wih1[r1 * IN + k0 + 8] : 0.f;
            float v19 = (k0 + 9 < IN) ? Wih1[r1 * IN + k0 + 9]
                      : (k0 + 9 == 11 ? (bih1[r1] + bhh1[r1]) : 0.f);
            w1i[t][0] = packb2(gs * v00, gs * v01);
            w1i[t][1] = packb2(gs * v10, gs * v11);
            w1i[t][2] = packb2(gs * v08, gs * v09);
            w1i[t][3] = packb2(gs * v18, gs * v19);
        }
        w1h[t][0] = packb2(gs * Whh1[r0 * 16 + k0],     gs * Whh1[r0 * 16 + k0 + 1]);
        w1h[t][1] = packb2(gs * Whh1[r1 * 16 + k0],     gs * Whh1[r1 * 16 + k0 + 1]);
        w1h[t][2] = packb2(gs * Whh1[r0 * 16 + k0 + 8], gs * Whh1[r0 * 16 + k0 + 9]);
        w1h[t][3] = packb2(gs * Whh1[r1 * 16 + k0 + 8], gs * Whh1[r1 * 16 + k0 + 9]);
        w2i[t][0] = packb2(gs * Wih2[r0 * 16 + k0],     gs * Wih2[r0 * 16 + k0 + 1]);
        w2i[t][1] = packb2(gs * Wih2[r1 * 16 + k0],     gs * Wih2[r1 * 16 + k0 + 1]);
        w2i[t][2] = packb2(gs * Wih2[r0 * 16 + k0 + 8], gs * Wih2[r0 * 16 + k0 + 9]);
        w2i[t][3] = packb2(gs * Wih2[r1 * 16 + k0 + 8], gs * Wih2[r1 * 16 + k0 + 9]);
        w2h[t][0] = packb2(gs * Whh2[r0 * 16 + k0],     gs * Whh2[r0 * 16 + k0 + 1]);
        w2h[t][1] = packb2(gs * Whh2[r1 * 16 + k0],     gs * Whh2[r1 * 16 + k0 + 1]);
        w2h[t][2] = packb2(gs * Whh2[r0 * 16 + k0 + 8], gs * Whh2[r0 * 16 + k0 + 9]);
        w2h[t][3] = packb2(gs * Whh2[r1 * 16 + k0 + 8], gs * Whh2[r1 * 16 + k0 + 9]);
        bs2f[t][0] = gs * (bih2[r0] + bhh2[r0]);
        bs2f[t][1] = gs * (bih2[r1] + bhh2[r1]);
    }

    // ---- x staging: each lane stages 2 elems (one per group) x 1 step ----
    const int seA = wid * 16 + (lane >> 2);       // group-A elem staged
    const int seB = seA + 8;                      // group-B elem staged
    const int ss  = lane & 3;
    const float* xpA = x + ((size_t)(eb + seA) * T + (ss + 1)) * IN;
    const float* xpB = x + ((size_t)(eb + seB) * T + (ss + 1)) * IN;

#define STAGE_ROW(PTR, SE, PH) do {                                       \
    float xr_[11];                                                        \
    _Pragma("unroll")                                                     \
    for (int i = 0; i < 11; ++i) xr_[i] = __ldg((PTR) + i);               \
    u32* d_ = &xs[PH][ss][SE][0];                                         \
    d_[0] = packb2(xr_[0], xr_[1]); d_[1] = packb2(xr_[2], xr_[3]);       \
    d_[2] = packb2(xr_[4], xr_[5]); d_[3] = packb2(xr_[6], xr_[7]);       \
    d_[4] = packb2(xr_[8], xr_[9]); d_[5] = packb2(xr_[10], 1.0f);        \
    d_[6] = 0u; d_[7] = 0u;                                               \
} while (0)

    STAGE_ROW(xpA, seA, 0);
    STAGE_ROW(xpB, seB, 0);
    __syncwarp();

    const int elwA = wid * 16 + g;       // group-A B-column elem
    const int elwB = elwA + 8;           // group-B

    // recurrent state, group A and group B
    u32 h1B0A = 0, h1B1A = 0, h2B0A = 0, h2B1A = 0;
    u32 c1p0A = 0, c1p1A = 0, c2p0A = 0, c2p1A = 0;
    u32 h2c0A = 0, h2c1A = 0;
    float ss0A = 0.f, ss1A = 0.f, ss2A = 0.f, ss3A = 0.f;
    u32 h1B0B = 0, h1B1B = 0, h2B0B = 0, h2B1B = 0;
    u32 c1p0B = 0, c1p1B = 0, c2p0B = 0, c2p1B = 0;
    u32 h2c0B = 0, h2c1B = 0;
    float ss0B = 0.f, ss1B = 0.f, ss2B = 0.f, ss3B = 0.f;

    // ---- prologue: h1(0) for both groups ----
#define PROLOGUE(ELW, C1P0, C1P1, H1B0, H1B1) do {                        \
    const float* x0_ = x + (size_t)(eb + (ELW)) * T * IN;                 \
    float v0_ = (k0     < IN) ? __ldg(x0_ + k0)     : 0.f;                \
    float v1_ = (k0 + 1 < IN) ? __ldg(x0_ + k0 + 1) : 0.f;                \
    float v8_ = (k0 + 8 < IN) ? __ldg(x0_ + k0 + 8) : 0.f;                \
    float v9_ = (k0 + 9 < IN) ? __ldg(x0_ + k0 + 9)                       \
              : (k0 + 9 == 11 ? 1.f : 0.f);                               \
    u32 xb0_ = packb2(v0_, v1_);                                          \
    u32 xb1_ = packb2(v8_, v9_);                                          \
    float A_[4][4];                                                       \
    _Pragma("unroll")                                                     \
    for (int t = 0; t < 4; ++t)                                           \
        mma_c(A_[t], w1i[t][0], w1i[t][1], w1i[t][2], w1i[t][3],          \
              xb0_, xb1_, 0.f, 0.f);                                      \
    u32 hc0_, hc1_;                                                       \
    LAYER_CELLS(A_, C1P0, C1P1, hc0_, hc1_);                              \
    H1B0 = movmat(hc0_);                                                  \
    H1B1 = movmat(hc1_);                                                  \
} while (0)

    PROLOGUE(elwA, c1p0A, c1p1A, h1B0A, h1B1A);
    PROLOGUE(elwB, c1p0B, c1p1B, h1B0B, h1B1B);

    // ---- main loop: iter i = 4c+s computes L2(i) || L1(i+1) for BOTH groups
    for (int c = 0; c < 128; ++c) {
        float xrA[11], xrB[11];
        if (c < 127) {
            const float* xqA = xpA + (size_t)(c + 1) * 4 * IN;
            const float* xqB = xpB + (size_t)(c + 1) * 4 * IN;
#pragma unroll
            for (int i = 0; i < 11; ++i) { xrA[i] = __ldg(xqA + i); xrB[i] = __ldg(xqB + i); }
        }

#pragma unroll
        for (int s = 0; s < 4; ++s) {
            if (c == 127 && s == 3) break;   // iter 511 in epilogue
            const u32* xrowA = &xs[c & 1][s][elwA][0];
            const u32* xrowB = &xs[c & 1][s][elwB][0];
            const u32 xb0A = xrowA[q], xb1A = xrowA[q + 4];
            const u32 xb0B = xrowB[q], xb1B = xrowB[q + 4];

            float A2g[4][4], A1g[4][4], B2g[4][4], B1g[4][4];
            GROUP_MMAS(A2g, A1g, h1B0A, h1B1A, h2B0A, h2B1A, xb0A, xb1A);
            GROUP_MMAS(B2g, B1g, h1B0B, h1B1B, h2B0B, h2B1B, xb0B, xb1B);

            // group A cells (B's MMAs complete during these MUFU chains)
            LAYER_CELLS(A2g, c2p0A, c2p1A, h2c0A, h2c1A);
            h2B0A = movmat(h2c0A); h2B1A = movmat(h2c1A);
            ss0A += ex2f(blo(h2c0A) * LOG2E);
            ss1A += ex2f(bhi(h2c0A) * LOG2E);
            ss2A += ex2f(blo(h2c1A) * LOG2E);
            ss3A += ex2f(bhi(h2c1A) * LOG2E);
            {
                u32 hc0_, hc1_;
                LAYER_CELLS(A1g, c1p0A, c1p1A, hc0_, hc1_);
                h1B0A = movmat(hc0_); h1B1A = movmat(hc1_);
            }

            // group B cells
            LAYER_CELLS(B2g, c2p0B, c2p1B, h2c0B, h2c1B);
            h2B0B = movmat(h2c0B); h2B1B = movmat(h2c1B);
            ss0B += ex2f(blo(h2c0B) * LOG2E);
            ss1B += ex2f(bhi(h2c0B) * LOG2E);
            ss2B += ex2f(blo(h2c1B) * LOG2E);
            ss3B += ex2f(bhi(h2c1B) * LOG2E);
            {
                u32 hc0_, hc1_;
                LAYER_CELLS(B1g, c1p0B, c1p1B, hc0_, hc1_);
                h1B0B = movmat(hc0_); h1B1B = movmat(hc1_);
            }
        }

        if (c < 127) {
            const int ph = (c + 1) & 1;
            u32* d_;
            d_ = &xs[ph][ss][seA][0];
            d_[0] = packb2(xrA[0], xrA[1]); d_[1] = packb2(xrA[2], xrA[3]);
            d_[2] = packb2(xrA[4], xrA[5]); d_[3] = packb2(xrA[6], xrA[7]);
            d_[4] = packb2(xrA[8], xrA[9]); d_[5] = packb2(xrA[10], 1.0f);
            d_[6] = 0u; d_[7] = 0u;
            d_ = &xs[ph][ss][seB][0];
            d_[0] = packb2(xrB[0], xrB[1]); d_[1] = packb2(xrB[2], xrB[3]);
            d_[2] = packb2(xrB[4], xrB[5]); d_[3] = packb2(xrB[6], xrB[7]);
            d_[4] = packb2(xrB[8], xrB[9]); d_[5] = packb2(xrB[10], 1.0f);
            d_[6] = 0u; d_[7] = 0u;
        }
        __syncwarp();
    }

    // ---- epilogue: L2(511) for both groups ----
#define EPILOGUE(H1B0, H1B1, H2B0, H2B1, C2P0, C2P1, H2C0, H2C1,          \
                 SS0, SS1, SS2, SS3) do {                                 \
    float A_[4][4];                                                       \
    _Pragma("unroll")                                                     \
    for (int t = 0; t < 4; ++t) {                                         \
        mma_c  (A_[t], w2i[t][0], w2i[t][1], w2i[t][2], w2i[t][3],        \
                H1B0, H1B1, bs2f[t][0], bs2f[t][1]);                      \
        mma_acc(A_[t], w2h[t][0], w2h[t][1], w2h[t][2], w2h[t][3],        \
                H2B0, H2B1);                                              \
    }                                                                     \
    LAYER_CELLS(A_, C2P0, C2P1, H2C0, H2C1);                              \
    SS0 += ex2f(blo(H2C0) * LOG2E);                                       \
    SS1 += ex2f(bhi(H2C0) * LOG2E);                                       \
    SS2 += ex2f(blo(H2C1) * LOG2E);                                       \
    SS3 += ex2f(bhi(H2C1) * LOG2E);                                       \
} while (0)

    EPILOGUE(h1B0A, h1B1A, h2B0A, h2B1A, c2p0A, c2p1A, h2c0A, h2c1A,
             ss0A, ss1A, ss2A, ss3A);
    EPILOGUE(h1B0B, h1B1B, h2B0B, h2B1B, c2p0B, c2p1B, h2c0B, h2c1B,
             ss0B, ss1B, ss2B, ss3B);

    // ---- s = exp(h2_last)/ssum; lane (g, q<2) owns (hcol g/g+8, batch 2q/2q+1)
    if (q < 2) {
        const int bA = wid * 16 + 2 * q;
        sbuf[bA]    [g]     = ex2f(blo(h2c0A) * LOG2E) * rcpf(ss0A);
        sbuf[bA + 1][g]     = ex2f(bhi(h2c0A) * LOG2E) * rcpf(ss1A);
        sbuf[bA]    [g + 8] = ex2f(blo(h2c1A) * LOG2E) * rcpf(ss2A);
        sbuf[bA + 1][g + 8] = ex2f(bhi(h2c1A) * LOG2E) * rcpf(ss3A);
        const int bB = bA + 8;
        sbuf[bB]    [g]     = ex2f(blo(h2c0B) * LOG2E) * rcpf(ss0B);
        sbuf[bB + 1][g]     = ex2f(bhi(h2c0B) * LOG2E) * rcpf(ss1B);
        sbuf[bB]    [g + 8] = ex2f(blo(h2c1B) * LOG2E) * rcpf(ss2B);
        sbuf[bB + 1][g + 8] = ex2f(bhi(h2c1B) * LOG2E) * rcpf(ss3B);
    }
    __syncwarp();

    // ---- dense head: lanes 0-15 handle the warp's 16 elems ----
    if (lane < 16) {
        const float* sr = &sbuf[wid * 16 + lane][0];
        float d1[8];
#pragma unroll
        for (int r = 0; r < 8; ++r) {
            float acc = bd1[r];
#pragma unroll
            for (int k = 0; k < 16; ++k)
                acc = fmaf(__ldg(Wd1 + r * 16 + k), sr[k], acc);
            d1[r] = acc;
        }
        float d2[8];
#pragma unroll
        for (int r = 0; r < 8; ++r) {
            float acc = bd2[r];
#pragma unroll
            for (int k = 0; k < 8; ++k)
                acc = fmaf(__ldg(Wd2 + r * 8 + k), d1[k], acc);
            d2[r] = acc;
        }
        float d3[3];
#pragma unroll
        for (int r = 0; r < 3; ++r) {
            float acc = bd3[r];
#pragma unroll
            for (int k = 0; k < 8; ++k)
                acc = fmaf(__ldg(Wd3 + r * 8 + k), d2[k], acc);
            d3[r] = acc;
        }
        float m  = fmaxf(d3[0], fmaxf(d3[1], d3[2]));
        float e0 = ex2f((d3[0] - m) * LOG2E);
        float e1 = ex2f((d3[1] - m) * LOG2E);
        float e2 = ex2f((d3[2] - m) * LOG2E);
        float inv = rcpf(e0 + e1 + e2);
        const int bg = eb + wid * 16 + lane;
        out[bg * 3 + 0] = e0 * inv;
        out[bg * 3 + 1] = e1 * inv;
        out[bg * 3 + 2] = e2 * inv;
    }
}

extern "C" void kernel_launch(void* const* d_in, const int* in_sizes, int n_in,
                              void* d_out, int out_size) {
    (void)in_sizes; (void)n_in; (void)out_size;
    const float* x    = (const float*)d_in[0];
    const float* Wih1 = (const float*)d_in[1];
    const float* Whh1 = (const float*)d_in[2];
    const float* bih1 = (const float*)d_in[3];
    const float* bhh1 = (const float*)d_in[4];
    const float* Wih2 = (const float*)d_in[5];
    const float* Whh2 = (const float*)d_in[6];
    const float* bih2 = (const float*)d_in[7];
    const float* bhh2 = (const float*)d_in[8];
    const float* Wd1  = (const float*)d_in[9];
    const float* bd1  = (const float*)d_in[10];
    const float* Wd2  = (const float*)d_in[11];
    const float* bd2  = (const float*)d_in[12];
    const float* Wd3  = (const float*)d_in[13];
    const float* bd3  = (const float*)d_in[14];
    float* out = (float*)d_out;

    // 4096 elems / (2 warps x 16 elems) = 128 CTAs of 64 threads.
    // Each warp runs TWO independent 8-elem recurrences (stall filling).
    lstm_mma_kernel<<<128, 64>>>(x, Wih1, Whh1, bih1, bhh1,
                                 Wih2, Whh2, bih2, bhh2,
                                 Wd1, bd1, Wd2, bd2, Wd3, bd3, out);
}

// round 16
// speedup vs baseline: 1.0099x; 1.0099x over previous
#include <cuda_runtime.h>
#include <cuda_bf16.h>

// Tensor-core LSTM, R16: dual-stream warps with SKEWED pipeline.
// Each warp owns 16 batch elements as two independent groups (A, B) of 8.
// Per iteration: MMAs(A,i) ; cells(B,i-1) ; MMAs(B,i) ; cells(A,i) —
// each group's MUFU/cell chain executes under the other group's in-flight
// tensor work (R15's grouped ordering serialized the pipes; this fixes it).
// Gates in M (4 m16 tiles), batch in N. 16 MMAs/group/step, movmatrix h
// relayout, f32 accumulators, packed bf16x2 cell math, bias via C operand.
// 128 CTAs x 64 thr. (Also fixes R15's q<2 softmax-store bug.)

#define FULLMASK 0xffffffffu
#define LOG2E 1.4426950408889634f
#define H2C 0x3F003F00u   /* bf16x2 {0.5, 0.5} */

typedef unsigned int u32;

static __device__ __forceinline__ u32 packb2(float lo, float hi) {
    u32 d;
    asm("cvt.rn.bf16x2.f32 %0, %1, %2;" : "=r"(d) : "f"(hi), "f"(lo));
    return d;
}
static __device__ __forceinline__ u32 tanhb2(u32 x) {
    u32 y; asm("tanh.approx.bf16x2 %0, %1;" : "=r"(y) : "r"(x)); return y;
}
static __device__ __forceinline__ u32 mulb2(u32 a, u32 b) {
    u32 d; asm("mul.rn.bf16x2 %0, %1, %2;" : "=r"(d) : "r"(a), "r"(b)); return d;
}
static __device__ __forceinline__ u32 fmab2(u32 a, u32 b, u32 c) {
    u32 d; asm("fma.rn.bf16x2 %0, %1, %2, %3;" : "=r"(d) : "r"(a), "r"(b), "r"(c));
    return d;
}
static __device__ __forceinline__ float blo(u32 v) {
    return __uint_as_float(v << 16);
}
static __device__ __forceinline__ float bhi(u32 v) {
    return __uint_as_float(v & 0xFFFF0000u);
}
static __device__ __forceinline__ float ex2f(float x) {
    float y; asm("ex2.approx.f32 %0, %1;" : "=f"(y) : "f"(x)); return y;
}
static __device__ __forceinline__ float rcpf(float x) {
    float y; asm("rcp.approx.f32 %0, %1;" : "=f"(y) : "f"(x)); return y;
}
static __device__ __forceinline__ u32 movmat(u32 a) {
    u32 d;
    asm("movmatrix.sync.aligned.m8n8.trans.b16 %0, %1;" : "=r"(d) : "r"(a));
    return d;
}

// D = A @ B + {c0,c0,c1,c1}  (row-bias splat: rows g / g+8 of the tile)
static __device__ __forceinline__ void mma_c(
    float* d, u32 a0, u32 a1, u32 a2, u32 a3, u32 b0, u32 b1,
    float c0, float c1)
{
    asm("mma.sync.aligned.m16n8k16.row.col.f32.bf16.bf16.f32 "
        "{%0,%1,%2,%3},{%4,%5,%6,%7},{%8,%9},{%10,%10,%11,%11};"
        : "=f"(d[0]), "=f"(d[1]), "=f"(d[2]), "=f"(d[3])
        : "r"(a0), "r"(a1), "r"(a2), "r"(a3), "r"(b0), "r"(b1),
          "f"(c0), "f"(c1));
}
static __device__ __forceinline__ void mma_acc(
    float* d, u32 a0, u32 a1, u32 a2, u32 a3, u32 b0, u32 b1)
{
    asm("mma.sync.aligned.m16n8k16.row.col.f32.bf16.bf16.f32 "
        "{%0,%1,%2,%3},{%4,%5,%6,%7},{%8,%9},{%0,%1,%2,%3};"
        : "+f"(d[0]), "+f"(d[1]), "+f"(d[2]), "+f"(d[3])
        : "r"(a0), "r"(a1), "r"(a2), "r"(a3), "r"(b0), "r"(b1));
}

// packed 2-cell LSTM update; i/f/o gates PRE-SCALED by 0.5
#define PCELL(IP, FP, GP, OP, CC, HH) do {                                \
    u32 si_ = fmab2(tanhb2(IP), H2C, H2C);                                \
    u32 sf_ = fmab2(tanhb2(FP), H2C, H2C);                                \
    u32 tg_ = tanhb2(GP);                                                 \
    u32 so_ = fmab2(tanhb2(OP), H2C, H2C);                                \
    CC = fmab2(sf_, CC, mulb2(si_, tg_));                                 \
    HH = mulb2(so_, tanhb2(CC));                                          \
} while (0)

#define LAYER_CELLS(D, CP0, CP1, HP0, HP1) do {                           \
    u32 iP0 = packb2(D[0][0], D[0][1]), iP1 = packb2(D[0][2], D[0][3]);   \
    u32 fP0 = packb2(D[1][0], D[1][1]), fP1 = packb2(D[1][2], D[1][3]);   \
    u32 gP0 = packb2(D[2][0], D[2][1]), gP1 = packb2(D[2][2], D[2][3]);   \
    u32 oP0 = packb2(D[3][0], D[3][1]), oP1 = packb2(D[3][2], D[3][3]);   \
    PCELL(iP0, fP0, gP0, oP0, CP0, HP0);                                  \
    PCELL(iP1, fP1, gP1, oP1, CP1, HP1);                                  \
} while (0)

// 16 MMAs of one group-step: L2(i) into D2, L1(i+1) into D1
#define GROUP_MMAS(D2, D1, H1B0, H1B1, H2B0, H2B1, XB0, XB1) do {         \
    _Pragma("unroll")                                                     \
    for (int t = 0; t < 4; ++t) {                                         \
        mma_c  (D2[t], w2i[t][0], w2i[t][1], w2i[t][2], w2i[t][3],        \
                H1B0, H1B1, bs2f[t][0], bs2f[t][1]);                      \
        mma_acc(D2[t], w2h[t][0], w2h[t][1], w2h[t][2], w2h[t][3],        \
                H2B0, H2B1);                                              \
        mma_c  (D1[t], w1h[t][0], w1h[t][1], w1h[t][2], w1h[t][3],        \
                H1B0, H1B1, 0.f, 0.f);                                    \
        mma_acc(D1[t], w1i[t][0], w1i[t][1], w1i[t][2], w1i[t][3],        \
                XB0, XB1);                                                \
    }                                                                     \
} while (0)

// full cell phase of one group-iteration: L2 cells -> h2(i) (+softmax acc),
// L1 cells -> h1(i+1), movmat relayouts for the next MMAs.
#define GROUP_CELLS(D2, D1, C2P0, C2P1, H2C0, H2C1, H2B0, H2B1,           \
                    C1P0, C1P1, H1B0, H1B1, SS0, SS1, SS2, SS3) do {      \
    LAYER_CELLS(D2, C2P0, C2P1, H2C0, H2C1);                              \
    H2B0 = movmat(H2C0); H2B1 = movmat(H2C1);                             \
    SS0 += ex2f(blo(H2C0) * LOG2E);                                       \
    SS1 += ex2f(bhi(H2C0) * LOG2E);                                       \
    SS2 += ex2f(blo(H2C1) * LOG2E);                                       \
    SS3 += ex2f(bhi(H2C1) * LOG2E);                                       \
    {                                                                     \
        u32 hc0_, hc1_;                                                   \
        LAYER_CELLS(D1, C1P0, C1P1, hc0_, hc1_);                          \
        H1B0 = movmat(hc0_); H1B1 = movmat(hc1_);                         \
    }                                                                     \
} while (0)

__global__ void __launch_bounds__(64)
lstm_mma_kernel(const float* __restrict__ x,
                const float* __restrict__ Wih1, const float* __restrict__ Whh1,
                const float* __restrict__ bih1, const float* __restrict__ bhh1,
                const float* __restrict__ Wih2, const float* __restrict__ Whh2,
                const float* __restrict__ bih2, const float* __restrict__ bhh2,
                const float* __restrict__ Wd1, const float* __restrict__ bd1,
                const float* __restrict__ Wd2, const float* __restrict__ bd2,
                const float* __restrict__ Wd3, const float* __restrict__ bd3,
                float* __restrict__ out)
{
    constexpr int T = 512, IN = 11;
    const int tid  = threadIdx.x;
    const int lane = tid & 31;
    const int wid  = tid >> 5;           // 0..1
    const int q    = lane & 3;
    const int g    = lane >> 2;
    const int k0   = q * 2;
    const int eb   = blockIdx.x * 32;

    __shared__ __align__(16) u32 xs[2][4][32][8];
    __shared__ float sbuf[32][16];

    // ---- weight A-fragments (shared by both groups) ----
    u32 w1i[4][4], w1h[4][4], w2i[4][4], w2h[4][4];
    float bs2f[4][2];
#pragma unroll
    for (int t = 0; t < 4; ++t) {
        const float gs = (t == 2) ? 1.0f : 0.5f;
        const int r0 = t * 16 + g, r1 = r0 + 8;
        {
            float v00 = (k0     < IN) ? Wih1[r0 * IN + k0]     : 0.f;
            float v01 = (k0 + 1 < IN) ? Wih1[r0 * IN + k0 + 1] : 0.f;
            float v10 = (k0     < IN) ? Wih1[r1 * IN + k0]     : 0.f;
            float v11 = (k0 + 1 < IN) ? Wih1[r1 * IN + k0 + 1] : 0.f;
            float v08 = (k0 + 8 < IN) ? Wih1[r0 * IN + k0 + 8] : 0.f;
            float v09 = (k0 + 9 < IN) ? Wih1[r0 * IN + k0 + 9]
                      : (k0 + 9 == 11 ? (bih1[r0] + bhh1[r0]) : 0.f);
            float v18 = (k0 + 8 < IN) ? Wih1[r1 * IN + k0 + 8] : 0.f;
            float v19 = (k0 + 9 < IN) ? Wih1[r1 * IN + k0 + 9]
                      : (k0 + 9 == 11 ? (bih1[r1] + bhh1[r1]) : 0.f);
            w1i[t][0] = packb2(gs * v00, gs * v01);
            w1i[t][1] = packb2(gs * v10, gs * v11);
            w1i[t][2] = packb2(gs * v08, gs * v09);
            w1i[t][3] = packb2(gs * v18, gs * v19);
        }
        w1h[t][0] = packb2(gs * Whh1[r0 * 16 + k0],     gs * Whh1[r0 * 16 + k0 + 1]);
        w1h[t][1] = packb2(gs * Whh1[r1 * 16 + k0],     gs * Whh1[r1 * 16 + k0 + 1]);
        w1h[t][2] = packb2(gs * Whh1[r0 * 16 + k0 + 8], gs * Whh1[r0 * 16 + k0 + 9]);
        w1h[t][3] = packb2(gs * Whh1[r1 * 16 + k0 + 8], gs * Whh1[r1 * 16 + k0 + 9]);
        w2i[t][0] = packb2(gs * Wih2[r0 * 16 + k0],     gs * Wih2[r0 * 16 + k0 + 1]);
        w2i[t][1] = packb2(gs * Wih2[r1 * 16 + k0],     gs * Wih2[r1 * 16 + k0 + 1]);
        w2i[t][2] = packb2(gs * Wih2[r0 * 16 + k0 + 8], gs * Wih2[r0 * 16 + k0 + 9]);
        w2i[t][3] = packb2(gs * Wih2[r1 * 16 + k0 + 8], gs * Wih2[r1 * 16 + k0 + 9]);
        w2h[t][0] = packb2(gs * Whh2[r0 * 16 + k0],     gs * Whh2[r0 * 16 + k0 + 1]);
        w2h[t][1] = packb2(gs * Whh2[r1 * 16 + k0],     gs * Whh2[r1 * 16 + k0 + 1]);
        w2h[t][2] = packb2(gs * Whh2[r0 * 16 + k0 + 8], gs * Whh2[r0 * 16 + k0 + 9]);
        w2h[t][3] = packb2(gs * Whh2[r1 * 16 + k0 + 8], gs * Whh2[r1 * 16 + k0 + 9]);
        bs2f[t][0] = gs * (bih2[r0] + bhh2[r0]);
        bs2f[t][1] = gs * (bih2[r1] + bhh2[r1]);
    }

    // ---- x staging: each lane stages 2 elems (one per group) x 1 step ----
    const int seA = wid * 16 + (lane >> 2);
    const int seB = seA + 8;
    const int ss  = lane & 3;
    const float* xpA = x + ((size_t)(eb + seA) * T + (ss + 1)) * IN;
    const float* xpB = x + ((size_t)(eb + seB) * T + (ss + 1)) * IN;

#define STAGE_ROW(PTR, SE, PH) do {                                       \
    float xr_[11];                                                        \
    _Pragma("unroll")                                                     \
    for (int i = 0; i < 11; ++i) xr_[i] = __ldg((PTR) + i);               \
    u32* d_ = &xs[PH][ss][SE][0];                                         \
    d_[0] = packb2(xr_[0], xr_[1]); d_[1] = packb2(xr_[2], xr_[3]);       \
    d_[2] = packb2(xr_[4], xr_[5]); d_[3] = packb2(xr_[6], xr_[7]);       \
    d_[4] = packb2(xr_[8], xr_[9]); d_[5] = packb2(xr_[10], 1.0f);        \
    d_[6] = 0u; d_[7] = 0u;                                               \
} while (0)

    STAGE_ROW(xpA, seA, 0);
    STAGE_ROW(xpB, seB, 0);
    __syncwarp();

    const int elwA = wid * 16 + g;
    const int elwB = elwA + 8;

    // recurrent state, groups A and B
    u32 h1B0A = 0, h1B1A = 0, h2B0A = 0, h2B1A = 0;
    u32 c1p0A = 0, c1p1A = 0, c2p0A = 0, c2p1A = 0;
    u32 h2c0A = 0, h2c1A = 0;
    float ss0A = 0.f, ss1A = 0.f, ss2A = 0.f, ss3A = 0.f;
    u32 h1B0B = 0, h1B1B = 0, h2B0B = 0, h2B1B = 0;
    u32 c1p0B = 0, c1p1B = 0, c2p0B = 0, c2p1B = 0;
    u32 h2c0B = 0, h2c1B = 0;
    float ss0B = 0.f, ss1B = 0.f, ss2B = 0.f, ss3B = 0.f;

    // persistent accumulator sets (pipeline registers)
    float AA2[4][4], AA1[4][4], BB2[4][4], BB1[4][4];

#define PROLOGUE(ELW, C1P0, C1P1, H1B0, H1B1) do {                        \
    const float* x0_ = x + (size_t)(eb + (ELW)) * T * IN;                 \
    float v0_ = (k0     < IN) ? __ldg(x0_ + k0)     : 0.f;                \
    float v1_ = (k0 + 1 < IN) ? __ldg(x0_ + k0 + 1) : 0.f;                \
    float v8_ = (k0 + 8 < IN) ? __ldg(x0_ + k0 + 8) : 0.f;                \
    float v9_ = (k0 + 9 < IN) ? __ldg(x0_ + k0 + 9)                       \
              : (k0 + 9 == 11 ? 1.f : 0.f);                               \
    u32 xb0_ = packb2(v0_, v1_);                                          \
    u32 xb1_ = packb2(v8_, v9_);                                          \
    float A_[4][4];                                                       \
    _Pragma("unroll")                                                     \
    for (int t = 0; t < 4; ++t)                                           \
        mma_c(A_[t], w1i[t][0], w1i[t][1], w1i[t][2], w1i[t][3],          \
              xb0_, xb1_, 0.f, 0.f);                                      \
    u32 hc0_, hc1_;                                                       \
    LAYER_CELLS(A_, C1P0, C1P1, hc0_, hc1_);                              \
    H1B0 = movmat(hc0_);                                                  \
    H1B1 = movmat(hc1_);                                                  \
} while (0)

    PROLOGUE(elwA, c1p0A, c1p1A, h1B0A, h1B1A);
    PROLOGUE(elwB, c1p0B, c1p1B, h1B0B, h1B1B);

    // ---- skewed main loop: iteration i = 4c+s (i = 0..510).
    //      order: MMAs(A,i) ; cells(B,i-1) ; MMAs(B,i) ; cells(A,i).
    for (int c = 0; c < 128; ++c) {
        float xrA[11], xrB[11];
        if (c < 127) {
            const float* xqA = xpA + (size_t)(c + 1) * 4 * IN;
            const float* xqB = xpB + (size_t)(c + 1) * 4 * IN;
#pragma unroll
            for (int i = 0; i < 11; ++i) { xrA[i] = __ldg(xqA + i); xrB[i] = __ldg(xqB + i); }
        }

#pragma unroll
        for (int s = 0; s < 4; ++s) {
            if (c == 127 && s == 3) break;   // iter 511 handled in epilogue
            const u32* xrowA = &xs[c & 1][s][elwA][0];
            const u32* xrowB = &xs[c & 1][s][elwB][0];
            const u32 xb0A = xrowA[q], xb1A = xrowA[q + 4];
            const u32 xb0B = xrowB[q], xb1B = xrowB[q + 4];

            // phase 1: issue A's tensor work
            GROUP_MMAS(AA2, AA1, h1B0A, h1B1A, h2B0A, h2B1A, xb0A, xb1A);

            // phase 2: B's cell math for the PREVIOUS iteration runs under
            // A's in-flight MMAs (skip on the very first iteration)
            if (!(c == 0 && s == 0)) {
                GROUP_CELLS(BB2, BB1, c2p0B, c2p1B, h2c0B, h2c1B,
                            h2B0B, h2B1B, c1p0B, c1p1B, h1B0B, h1B1B,
                            ss0B, ss1B, ss2B, ss3B);
            }

            // phase 3: issue B's tensor work (uses h just updated above)
            GROUP_MMAS(BB2, BB1, h1B0B, h1B1B, h2B0B, h2B1B, xb0B, xb1B);

            // phase 4: A's cell math runs under B's in-flight MMAs
            GROUP_CELLS(AA2, AA1, c2p0A, c2p1A, h2c0A, h2c1A,
                        h2B0A, h2B1A, c1p0A, c1p1A, h1B0A, h1B1A,
                        ss0A, ss1A, ss2A, ss3A);
        }

        if (c < 127) {
            const int ph = (c + 1) & 1;
            u32* d_;
            d_ = &xs[ph][ss][seA][0];
            d_[0] = packb2(xrA[0], xrA[1]); d_[1] = packb2(xrA[2], xrA[3]);
            d_[2] = packb2(xrA[4], xrA[5]); d_[3] = packb2(xrA[6], xrA[7]);
            d_[4] = packb2(xrA[8], xrA[9]); d_[5] = packb2(xrA[10], 1.0f);
            d_[6] = 0u; d_[7] = 0u;
            d_ = &xs[ph][ss][seB][0];
            d_[0] = packb2(xrB[0], xrB[1]); d_[1] = packb2(xrB[2], xrB[3]);
            d_[2] = packb2(xrB[4], xrB[5]); d_[3] = packb2(xrB[6], xrB[7]);
            d_[4] = packb2(xrB[8], xrB[9]); d_[5] = packb2(xrB[10], 1.0f);
            d_[6] = 0u; d_[7] = 0u;
        }
        __syncwarp();
    }

    // ---- drain: B's cells for iteration 510 ----
    GROUP_CELLS(BB2, BB1, c2p0B, c2p1B, h2c0B, h2c1B,
                h2B0B, h2B1B, c1p0B, c1p1B, h1B0B, h1B1B,
                ss0B, ss1B, ss2B, ss3B);

    // ---- epilogue: L2(511) for both groups ----
#define EPILOGUE(H1B0, H1B1, H2B0, H2B1, C2P0, C2P1, H2C0, H2C1,          \
                 SS0, SS1, SS2, SS3) do {                                 \
    float A_[4][4];                                                       \
    _Pragma("unroll")                                                     \
    for (int t = 0; t < 4; ++t) {                                         \
        mma_c  (A_[t], w2i[t][0], w2i[t][1], w2i[t][2], w2i[t][3],        \
                H1B0, H1B1, bs2f[t][0], bs2f[t][1]);                      \
        mma_acc(A_[t], w2h[t][0], w2h[t][1], w2h[t][2], w2h[t][3],        \
                H2B0, H2B1);                                              \
    }                                                                     \
    LAYER_CELLS(A_, C2P0, C2P1, H2C0, H2C1);                              \
    SS0 += ex2f(blo(H2C0) * LOG2E);                                       \
    SS1 += ex2f(bhi(H2C0) * LOG2E);                                       \
    SS2 += ex2f(blo(H2C1) * LOG2E);                                       \
    SS3 += ex2f(bhi(H2C1) * LOG2E);                                       \
} while (0)

    EPILOGUE(h1B0A, h1B1A, h2B0A, h2B1A, c2p0A, c2p1A, h2c0A, h2c1A,
             ss0A, ss1A, ss2A, ss3A);
    EPILOGUE(h1B0B, h1B1B, h2B0B, h2B1B, c2p0B, c2p1B, h2c0B, h2c1B,
             ss0B, ss1B, ss2B, ss3B);

    // ---- s = exp(h2_last)/ssum. ALL lanes store (fixes R15's q<2 bug):
    //      lane (g,q) owns hcols g/g+8 for batches 2q, 2q+1 of each group.
    {
        const int bA = wid * 16 + 2 * q;
        sbuf[bA]    [g]     = ex2f(blo(h2c0A) * LOG2E) * rcpf(ss0A);
        sbuf[bA + 1][g]     = ex2f(bhi(h2c0A) * LOG2E) * rcpf(ss1A);
        sbuf[bA]    [g + 8] = ex2f(blo(h2c1A) * LOG2E) * rcpf(ss2A);
        sbuf[bA + 1][g + 8] = ex2f(bhi(h2c1A) * LOG2E) * rcpf(ss3A);
        const int bB = bA + 8;
        sbuf[bB]    [g]     = ex2f(blo(h2c0B) * LOG2E) * rcpf(ss0B);
        sbuf[bB + 1][g]     = ex2f(bhi(h2c0B) * LOG2E) * rcpf(ss1B);
        sbuf[bB]    [g + 8] = ex2f(blo(h2c1B) * LOG2E) * rcpf(ss2B);
        sbuf[bB + 1][g + 8] = ex2f(bhi(h2c1B) * LOG2E) * rcpf(ss3B);
    }
    __syncwarp();

    // ---- dense head: lanes 0-15 handle the warp's 16 elems ----
    if (lane < 16) {
        const float* sr = &sbuf[wid * 16 + lane][0];
        float d1[8];
#pragma unroll
        for (int r = 0; r < 8; ++r) {
            float acc = bd1[r];
#pragma unroll
            for (int k = 0; k < 16; ++k)
                acc = fmaf(__ldg(Wd1 + r * 16 + k), sr[k], acc);
            d1[r] = acc;
        }
        float d2[8];
#pragma unroll
        for (int r = 0; r < 8; ++r) {
            float acc = bd2[r];
#pragma unroll
            for (int k = 0; k < 8; ++k)
                acc = fmaf(__ldg(Wd2 + r * 8 + k), d1[k], acc);
            d2[r] = acc;
        }
        float d3[3];
#pragma unroll
        for (int r = 0; r < 3; ++r) {
            float acc = bd3[r];
#pragma unroll
            for (int k = 0; k < 8; ++k)
                acc = fmaf(__ldg(Wd3 + r * 8 + k), d2[k], acc);
            d3[r] = acc;
        }
        float m  = fmaxf(d3[0], fmaxf(d3[1], d3[2]));
        float e0 = ex2f((d3[0] - m) * LOG2E);
        float e1 = ex2f((d3[1] - m) * LOG2E);
        float e2 = ex2f((d3[2] - m) * LOG2E);
        float inv = rcpf(e0 + e1 + e2);
        const int bg = eb + wid * 16 + lane;
        out[bg * 3 + 0] = e0 * inv;
        out[bg * 3 + 1] = e1 * inv;
        out[bg * 3 + 2] = e2 * inv;
    }
}

extern "C" void kernel_launch(void* const* d_in, const int* in_sizes, int n_in,
                              void* d_out, int out_size) {
    (void)in_sizes; (void)n_in; (void)out_size;
    const float* x    = (const float*)d_in[0];
    const float* Wih1 = (const float*)d_in[1];
    const float* Whh1 = (const float*)d_in[2];
    const float* bih1 = (const float*)d_in[3];
    const float* bhh1 = (const float*)d_in[4];
    const float* Wih2 = (const float*)d_in[5];
    const float* Whh2 = (const float*)d_in[6];
    const float* bih2 = (const float*)d_in[7];
    const float* bhh2 = (const float*)d_in[8];
    const float* Wd1  = (const float*)d_in[9];
    const float* bd1  = (const float*)d_in[10];
    const float* Wd2  = (const float*)d_in[11];
    const float* bd2  = (const float*)d_in[12];
    const float* Wd3  = (const float*)d_in[13];
    const float* bd3  = (const float*)d_in[14];
    float* out = (float*)d_out;

    // 4096 elems / (2 warps x 16 elems) = 128 CTAs of 64 threads.
    // Each warp: two 8-elem recurrences, SKEW-pipelined across pipes.
    lstm_mma_kernel<<<128, 64>>>(x, Wih1, Whh1, bih1, bhh1,
                                 Wih2, Whh2, bih2, bhh2,
                                 Wd1, bd1, Wd2, bd2, Wd3, bd3, out);
}

// round 17
// speedup vs baseline: 1.5104x; 1.4956x over previous
#include <cuda_runtime.h>
#include <cuda_bf16.h>

// Tensor-core LSTM, R17 = R13 + split MMA accumulators.
// Gates in M (4 m16 tiles: i,f,g,o), batch in N (8 elems/warp), 16 MMAs/step.
// Each tile's two matmuls write INDEPENDENT accumulators (merged by FADD at
// the pack stage) — removes the serial mma_c->mma_acc HMMA dependency that
// sat on the critical path. movmatrix h relayout, f32 accumulators, packed
// bf16x2 cell math, L2(i) || L1(i+1) pipeline, 128 CTAs x 128 thr (1 wave).

#define FULLMASK 0xffffffffu
#define LOG2E 1.4426950408889634f
#define H2C 0x3F003F00u   /* bf16x2 {0.5, 0.5} */

typedef unsigned int u32;

static __device__ __forceinline__ u32 packb2(float lo, float hi) {
    u32 d;
    asm("cvt.rn.bf16x2.f32 %0, %1, %2;" : "=r"(d) : "f"(hi), "f"(lo));
    return d;
}
static __device__ __forceinline__ u32 tanhb2(u32 x) {
    u32 y; asm("tanh.approx.bf16x2 %0, %1;" : "=r"(y) : "r"(x)); return y;
}
static __device__ __forceinline__ u32 mulb2(u32 a, u32 b) {
    u32 d; asm("mul.rn.bf16x2 %0, %1, %2;" : "=r"(d) : "r"(a), "r"(b)); return d;
}
static __device__ __forceinline__ u32 fmab2(u32 a, u32 b, u32 c) {
    u32 d; asm("fma.rn.bf16x2 %0, %1, %2, %3;" : "=r"(d) : "r"(a), "r"(b), "r"(c));
    return d;
}
static __device__ __forceinline__ float blo(u32 v) {
    return __uint_as_float(v << 16);
}
static __device__ __forceinline__ float bhi(u32 v) {
    return __uint_as_float(v & 0xFFFF0000u);
}
static __device__ __forceinline__ float ex2f(float x) {
    float y; asm("ex2.approx.f32 %0, %1;" : "=f"(y) : "f"(x)); return y;
}
static __device__ __forceinline__ float rcpf(float x) {
    float y; asm("rcp.approx.f32 %0, %1;" : "=f"(y) : "f"(x)); return y;
}
// warp-collective 8x8 b16 transpose (C-fragment -> B-fragment relayout)
static __device__ __forceinline__ u32 movmat(u32 a) {
    u32 d;
    asm("movmatrix.sync.aligned.m8n8.trans.b16 %0, %1;" : "=r"(d) : "r"(a));
    return d;
}

// D = A @ B + {c0,c0,c1,c1}  (row-bias splat: rows g / g+8 of the tile)
static __device__ __forceinline__ void mma_c(
    float* d, u32 a0, u32 a1, u32 a2, u32 a3, u32 b0, u32 b1,
    float c0, float c1)
{
    asm("mma.sync.aligned.m16n8k16.row.col.f32.bf16.bf16.f32 "
        "{%0,%1,%2,%3},{%4,%5,%6,%7},{%8,%9},{%10,%10,%11,%11};"
        : "=f"(d[0]), "=f"(d[1]), "=f"(d[2]), "=f"(d[3])
        : "r"(a0), "r"(a1), "r"(a2), "r"(a3), "r"(b0), "r"(b1),
          "f"(c0), "f"(c1));
}
// D = A @ B (zero C) — used for the split second accumulator
static __device__ __forceinline__ void mma_z(
    float* d, u32 a0, u32 a1, u32 a2, u32 a3, u32 b0, u32 b1)
{
    asm("mma.sync.aligned.m16n8k16.row.col.f32.bf16.bf16.f32 "
        "{%0,%1,%2,%3},{%4,%5,%6,%7},{%8,%9},{%10,%10,%10,%10};"
        : "=f"(d[0]), "=f"(d[1]), "=f"(d[2]), "=f"(d[3])
        : "r"(a0), "r"(a1), "r"(a2), "r"(a3), "r"(b0), "r"(b1),
          "f"(0.f));
}

// packed 2-cell LSTM update; i/f/o gates PRE-SCALED by 0.5:
// sigmoid = fma(tanh(gate), 0.5, 0.5). Pairs run over two batch elems.
#define PCELL(IP, FP, GP, OP, CC, HH) do {                                \
    u32 si_ = fmab2(tanhb2(IP), H2C, H2C);                                \
    u32 sf_ = fmab2(tanhb2(FP), H2C, H2C);                                \
    u32 tg_ = tanhb2(GP);                                                 \
    u32 so_ = fmab2(tanhb2(OP), H2C, H2C);                                \
    CC = fmab2(sf_, CC, mulb2(si_, tg_));                                 \
    HH = mulb2(so_, tanhb2(CC));                                          \
} while (0)

// merge two split accumulator sets (FADD) + pack + both PCELLs of one layer.
#define LAYER_CELLS2(D, E, CP0, CP1, HP0, HP1) do {                       \
    u32 iP0 = packb2(D[0][0] + E[0][0], D[0][1] + E[0][1]);               \
    u32 iP1 = packb2(D[0][2] + E[0][2], D[0][3] + E[0][3]);               \
    u32 fP0 = packb2(D[1][0] + E[1][0], D[1][1] + E[1][1]);               \
    u32 fP1 = packb2(D[1][2] + E[1][2], D[1][3] + E[1][3]);               \
    u32 gP0 = packb2(D[2][0] + E[2][0], D[2][1] + E[2][1]);               \
    u32 gP1 = packb2(D[2][2] + E[2][2], D[2][3] + E[2][3]);               \
    u32 oP0 = packb2(D[3][0] + E[3][0], D[3][1] + E[3][1]);               \
    u32 oP1 = packb2(D[3][2] + E[3][2], D[3][3] + E[3][3]);               \
    PCELL(iP0, fP0, gP0, oP0, CP0, HP0);                                  \
    PCELL(iP1, fP1, gP1, oP1, CP1, HP1);                                  \
} while (0)

// single-set variant (prologue/epilogue paths)
#define LAYER_CELLS(D, CP0, CP1, HP0, HP1) do {                           \
    u32 iP0 = packb2(D[0][0], D[0][1]), iP1 = packb2(D[0][2], D[0][3]);   \
    u32 fP0 = packb2(D[1][0], D[1][1]), fP1 = packb2(D[1][2], D[1][3]);   \
    u32 gP0 = packb2(D[2][0], D[2][1]), gP1 = packb2(D[2][2], D[2][3]);   \
    u32 oP0 = packb2(D[3][0], D[3][1]), oP1 = packb2(D[3][2], D[3][3]);   \
    PCELL(iP0, fP0, gP0, oP0, CP0, HP0);                                  \
    PCELL(iP1, fP1, gP1, oP1, CP1, HP1);                                  \
} while (0)

__global__ void __launch_bounds__(128)
lstm_mma_kernel(const float* __restrict__ x,
                const float* __restrict__ Wih1, const float* __restrict__ Whh1,
                const float* __restrict__ bih1, const float* __restrict__ bhh1,
                const float* __restrict__ Wih2, const float* __restrict__ Whh2,
                const float* __restrict__ bih2, const float* __restrict__ bhh2,
                const float* __restrict__ Wd1, const float* __restrict__ bd1,
                const float* __restrict__ Wd2, const float* __restrict__ bd2,
                const float* __restrict__ Wd3, const float* __restrict__ bd3,
                float* __restrict__ out)
{
    constexpr int T = 512, IN = 11;
    const int tid  = threadIdx.x;
    const int lane = tid & 31;
    const int wid  = tid >> 5;           // 0..3
    const int q    = lane & 3;
    const int g    = lane >> 2;
    const int k0   = q * 2;
    const int eb   = blockIdx.x * 32;    // CTA batch base (32 elems)

    // x staging: [phase][step-in-chunk][elem][8 bf16x2]; chunk c holds t=4c+1..4c+4
    __shared__ __align__(16) u32 xs[2][4][32][8];
    __shared__ float sbuf[32][16];

    // ---- weight A-fragments (m16k16 row-major): tile t = gate (i,f,g,o),
    //      rows t*16+g / t*16+g+8; 0.5 folded into i/f/o; L1 bias at K=11 ----
    u32 w1i[4][4], w1h[4][4], w2i[4][4], w2h[4][4];
    float bs2f[4][2];
#pragma unroll
    for (int t = 0; t < 4; ++t) {
        const float gs = (t == 2) ? 1.0f : 0.5f;
        const int r0 = t * 16 + g, r1 = r0 + 8;
        {
            float v00 = (k0     < IN) ? Wih1[r0 * IN + k0]     : 0.f;
            float v01 = (k0 + 1 < IN) ? Wih1[r0 * IN + k0 + 1] : 0.f;
            float v10 = (k0     < IN) ? Wih1[r1 * IN + k0]     : 0.f;
            float v11 = (k0 + 1 < IN) ? Wih1[r1 * IN + k0 + 1] : 0.f;
            float v08 = (k0 + 8 < IN) ? Wih1[r0 * IN + k0 + 8] : 0.f;
            float v09 = (k0 + 9 < IN) ? Wih1[r0 * IN + k0 + 9]
                      : (k0 + 9 == 11 ? (bih1[r0] + bhh1[r0]) : 0.f);
            float v18 = (k0 + 8 < IN) ? Wih1[r1 * IN + k0 + 8] : 0.f;
            float v19 = (k0 + 9 < IN) ? Wih1[r1 * IN + k0 + 9]
                      : (k0 + 9 == 11 ? (bih1[r1] + bhh1[r1]) : 0.f);
            w1i[t][0] = packb2(gs * v00, gs * v01);
            w1i[t][1] = packb2(gs * v10, gs * v11);
            w1i[t][2] = packb2(gs * v08, gs * v09);
            w1i[t][3] = packb2(gs * v18, gs * v19);
        }
        w1h[t][0] = packb2(gs * Whh1[r0 * 16 + k0],     gs * Whh1[r0 * 16 + k0 + 1]);
        w1h[t][1] = packb2(gs * Whh1[r1 * 16 + k0],     gs * Whh1[r1 * 16 + k0 + 1]);
        w1h[t][2] = packb2(gs * Whh1[r0 * 16 + k0 + 8], gs * Whh1[r0 * 16 + k0 + 9]);
        w1h[t][3] = packb2(gs * Whh1[r1 * 16 + k0 + 8], gs * Whh1[r1 * 16 + k0 + 9]);
        w2i[t][0] = packb2(gs * Wih2[r0 * 16 + k0],     gs * Wih2[r0 * 16 + k0 + 1]);
        w2i[t][1] = packb2(gs * Wih2[r1 * 16 + k0],     gs * Wih2[r1 * 16 + k0 + 1]);
        w2i[t][2] = packb2(gs * Wih2[r0 * 16 + k0 + 8], gs * Wih2[r0 * 16 + k0 + 9]);
        w2i[t][3] = packb2(gs * Wih2[r1 * 16 + k0 + 8], gs * Wih2[r1 * 16 + k0 + 9]);
        w2h[t][0] = packb2(gs * Whh2[r0 * 16 + k0],     gs * Whh2[r0 * 16 + k0 + 1]);
        w2h[t][1] = packb2(gs * Whh2[r1 * 16 + k0],     gs * Whh2[r1 * 16 + k0 + 1]);
        w2h[t][2] = packb2(gs * Whh2[r0 * 16 + k0 + 8], gs * Whh2[r0 * 16 + k0 + 9]);
        w2h[t][3] = packb2(gs * Whh2[r1 * 16 + k0 + 8], gs * Whh2[r1 * 16 + k0 + 9]);
        bs2f[t][0] = gs * (bih2[r0] + bhh2[r0]);
        bs2f[t][1] = gs * (bih2[r1] + bhh2[r1]);
    }

    // ---- x staging: thread -> (elem = tid>>2, step-in-chunk = tid&3) ----
    const int se = tid >> 2;             // 0..31 (CTA-local elem)
    const int ss = tid & 3;
    const float* xp = x + ((size_t)(eb + se) * T + (ss + 1)) * IN;

    // stage chunk 0 (t = 1..4); x[11] slot = 1.0 carries the layer-1 bias
    {
        float xr[11];
#pragma unroll
        for (int i = 0; i < 11; ++i) xr[i] = __ldg(xp + i);
        u32* d = &xs[0][ss][se][0];
        d[0] = packb2(xr[0], xr[1]); d[1] = packb2(xr[2], xr[3]);
        d[2] = packb2(xr[4], xr[5]); d[3] = packb2(xr[6], xr[7]);
        d[4] = packb2(xr[8], xr[9]); d[5] = packb2(xr[10], 1.0f);
        d[6] = 0u; d[7] = 0u;
    }
    __syncwarp();

    const int elw = wid * 8 + g;         // this lane's B-column batch elem

    // recurrent state
    u32 h1B0 = 0, h1B1 = 0, h2B0 = 0, h2B1 = 0;
    u32 c1p0 = 0, c1p1 = 0, c2p0 = 0, c2p1 = 0;
    u32 h2c0 = 0, h2c1 = 0;              // h2 in C layout (for softmax)
    float ss0 = 0.f, ss1 = 0.f, ss2 = 0.f, ss3 = 0.f;

    // ---- prologue: h1(0) = cell(Wih1·x(0) + b1) ----
    {
        const float* x0 = x + (size_t)(eb + elw) * T * IN;
        float v0 = (k0     < IN) ? __ldg(x0 + k0)     : 0.f;
        float v1 = (k0 + 1 < IN) ? __ldg(x0 + k0 + 1) : 0.f;
        float v8 = (k0 + 8 < IN) ? __ldg(x0 + k0 + 8) : 0.f;
        float v9 = (k0 + 9 < IN) ? __ldg(x0 + k0 + 9) : (k0 + 9 == 11 ? 1.f : 0.f);
        u32 xb0 = packb2(v0, v1);
        u32 xb1 = packb2(v8, v9);
        float A[4][4];
#pragma unroll
        for (int t = 0; t < 4; ++t)
            mma_c(A[t], w1i[t][0], w1i[t][1], w1i[t][2], w1i[t][3],
                  xb0, xb1, 0.f, 0.f);
        u32 h1c0, h1c1;
        LAYER_CELLS(A, c1p0, c1p1, h1c0, h1c1);
        h1B0 = movmat(h1c0);
        h1B1 = movmat(h1c1);
    }

    // ---- main loop: iter i = 4c+s computes L2(i) || L1(i+1); skip i=511 ----
    for (int c = 0; c < 128; ++c) {
        float xr[11] = {0,0,0,0,0,0,0,0,0,0,0};
        if (c < 127) {
            const float* xq = xp + (size_t)(c + 1) * 4 * IN;   // t = 4c+ss+5
            if (4 * c + ss + 5 < T) {
#pragma unroll
                for (int i = 0; i < 11; ++i) xr[i] = __ldg(xq + i);
            }
        }

#pragma unroll
        for (int s = 0; s < 4; ++s) {
            if (c == 127 && s == 3) break;   // iter 511 handled in epilogue
            const u32* xrow = &xs[c & 1][s][elw][0];
            const u32 xb0 = xrow[q];
            const u32 xb1 = xrow[q + 4];

            // 16 MMAs, all FULLY independent (split accumulators):
            //   A  = w2i·h1 + bias2     Ap = w2h·h2
            //   Bq = w1h·h1             Bp = w1i·x (+bias1 via x[11])
            float A[4][4], Ap[4][4], Bq[4][4], Bp[4][4];
#pragma unroll
            for (int t = 0; t < 4; ++t) {
                mma_c(A[t],  w2i[t][0], w2i[t][1], w2i[t][2], w2i[t][3],
                      h1B0, h1B1, bs2f[t][0], bs2f[t][1]);
                mma_z(Ap[t], w2h[t][0], w2h[t][1], w2h[t][2], w2h[t][3],
                      h2B0, h2B1);
                mma_z(Bq[t], w1h[t][0], w1h[t][1], w1h[t][2], w1h[t][3],
                      h1B0, h1B1);
                mma_z(Bp[t], w1i[t][0], w1i[t][1], w1i[t][2], w1i[t][3],
                      xb0, xb1);
            }

            // L2 cell -> h2(i); FADD merge at pack stage
            LAYER_CELLS2(A, Ap, c2p0, c2p1, h2c0, h2c1);
            h2B0 = movmat(h2c0);
            h2B1 = movmat(h2c1);
            ss0 += ex2f(blo(h2c0) * LOG2E);
            ss1 += ex2f(bhi(h2c0) * LOG2E);
            ss2 += ex2f(blo(h2c1) * LOG2E);
            ss3 += ex2f(bhi(h2c1) * LOG2E);

            // L1 cell -> h1(i+1)
            u32 h1c0, h1c1;
            LAYER_CELLS2(Bq, Bp, c1p0, c1p1, h1c0, h1c1);
            h1B0 = movmat(h1c0);
            h1B1 = movmat(h1c1);
        }

        if (c < 127) {
            u32* d = &xs[(c + 1) & 1][ss][se][0];
            d[0] = packb2(xr[0], xr[1]); d[1] = packb2(xr[2], xr[3]);
            d[2] = packb2(xr[4], xr[5]); d[3] = packb2(xr[6], xr[7]);
            d[4] = packb2(xr[8], xr[9]); d[5] = packb2(xr[10], 1.0f);
            d[6] = 0u; d[7] = 0u;
        }
        __syncwarp();
    }

    // ---- epilogue: L2(511) ----
    {
        float A[4][4], Ap[4][4];
#pragma unroll
        for (int t = 0; t < 4; ++t) {
            mma_c(A[t],  w2i[t][0], w2i[t][1], w2i[t][2], w2i[t][3],
                  h1B0, h1B1, bs2f[t][0], bs2f[t][1]);
            mma_z(Ap[t], w2h[t][0], w2h[t][1], w2h[t][2], w2h[t][3],
                  h2B0, h2B1);
        }
        LAYER_CELLS2(A, Ap, c2p0, c2p1, h2c0, h2c1);
        ss0 += ex2f(blo(h2c0) * LOG2E);
        ss1 += ex2f(bhi(h2c0) * LOG2E);
        ss2 += ex2f(blo(h2c1) * LOG2E);
        ss3 += ex2f(bhi(h2c1) * LOG2E);
    }

    // ---- s = exp(h2_last)/ssum; lane (g,q) owns (hcol g/g+8, batch 2q/2q+1)
    {
        const int b0i = wid * 8 + 2 * q;
        sbuf[b0i]    [g]     = ex2f(blo(h2c0) * LOG2E) * rcpf(ss0);
        sbuf[b0i + 1][g]     = ex2f(bhi(h2c0) * LOG2E) * rcpf(ss1);
        sbuf[b0i]    [g + 8] = ex2f(blo(h2c1) * LOG2E) * rcpf(ss2);
        sbuf[b0i + 1][g + 8] = ex2f(bhi(h2c1) * LOG2E) * rcpf(ss3);
    }
    __syncwarp();

    // ---- dense head: lanes 0-7 of each warp handle its 8 elems ----
    if (lane < 8) {
        const float* sr = &sbuf[wid * 8 + lane][0];
        float d1[8];
#pragma unroll
        for (int r = 0; r < 8; ++r) {
            float acc = bd1[r];
#pragma unroll
            for (int k = 0; k < 16; ++k)
                acc = fmaf(__ldg(Wd1 + r * 16 + k), sr[k], acc);
            d1[r] = acc;
        }
        float d2[8];
#pragma unroll
        for (int r = 0; r < 8; ++r) {
            float acc = bd2[r];
#pragma unroll
            for (int k = 0; k < 8; ++k)
                acc = fmaf(__ldg(Wd2 + r * 8 + k), d1[k], acc);
            d2[r] = acc;
        }
        float d3[3];
#pragma unroll
        for (int r = 0; r < 3; ++r) {
            float acc = bd3[r];
#pragma unroll
            for (int k = 0; k < 8; ++k)
                acc = fmaf(__ldg(Wd3 + r * 8 + k), d2[k], acc);
            d3[r] = acc;
        }
        float m  = fmaxf(d3[0], fmaxf(d3[1], d3[2]));
        float e0 = ex2f((d3[0] - m) * LOG2E);
        float e1 = ex2f((d3[1] - m) * LOG2E);
        float e2 = ex2f((d3[2] - m) * LOG2E);
        float inv = rcpf(e0 + e1 + e2);
        const int bg = eb + wid * 8 + lane;
        out[bg * 3 + 0] = e0 * inv;
        out[bg * 3 + 1] = e1 * inv;
        out[bg * 3 + 2] = e2 * inv;
    }
}

extern "C" void kernel_launch(void* const* d_in, const int* in_sizes, int n_in,
                              void* d_out, int out_size) {
    (void)in_sizes; (void)n_in; (void)out_size;
    const float* x    = (const float*)d_in[0];
    const float* Wih1 = (const float*)d_in[1];
    const float* Whh1 = (const float*)d_in[2];
    const float* bih1 = (const float*)d_in[3];
    const float* bhh1 = (const float*)d_in[4];
    const float* Wih2 = (const float*)d_in[5];
    const float* Whh2 = (const float*)d_in[6];
    const float* bih2 = (const float*)d_in[7];
    const float* bhh2 = (const float*)d_in[8];
    const float* Wd1  = (const float*)d_in[9];
    const float* bd1  = (const float*)d_in[10];
    const float* Wd2  = (const float*)d_in[11];
    const float* bd2  = (const float*)d_in[12];
    const float* Wd3  = (const float*)d_in[13];
    const float* bd3  = (const float*)d_in[14];
    float* out = (float*)d_out;

    // 4096 elems / (4 warps x 8 elems) = 128 CTAs — full SM coverage, 1 wave
    lstm_mma_kernel<<<128, 128>>>(x, Wih1, Whh1, bih1, bhh1,
                                  Wih2, Whh2, bih2, bhh2,
                                  Wd1, bd1, Wd2, bd2, Wd3, bd3, out);
}